// round 5
// baseline (speedup 1.0000x reference)
#include <cuda_runtime.h>
#include <cuda_bf16.h>

// Problem constants
#define O_CH   256
#define C_IN   128
#define K_H    24
#define N_IN   24
#define N_OUT  24
#define KS     5

#define WH_ELEMS  18874368     // 256*24*128*24
#define WRN_ELEMS 768000       // 256*24*125

#define NB_WRN 500             // 500 blocks * 384 thr * 4 elem = 768000
#define NB_WH  1024            // 256 o * 4 quarters
#define NTHREADS 384

// ---------------------------------------------------------------------------
// Single fused kernel.
//   blocks [0, NB_WRN):            wRn trilinear sampling (no shared needed)
//   blocks [NB_WRN, NB_WRN+NB_WH): wH gather; each block recomputes the 144
//                                  nn indices it needs (6 a-values x 24 b)
//                                  while its 12KB weight stage is in flight.
// ---------------------------------------------------------------------------
__global__ void __launch_bounds__(NTHREADS)
fused_kernel(const float* __restrict__ in_H,
             const float* __restrict__ out_H,
             const float* __restrict__ grid_H,
             const float* __restrict__ grid_Rn,
             const float* __restrict__ weight_H,
             const float* __restrict__ weight_Rn,
             float* __restrict__ out) {
    int bid = blockIdx.x;
    int tid = threadIdx.x;

    if (bid < NB_WRN) {
        // ================= wRn role =================
        float* wout = out + WH_ELEMS;
        int base = bid * (NTHREADS * 4);

        #pragma unroll
        for (int k = 0; k < 4; k++) {
            int idx = base + k * NTHREADS + tid;   // < WRN_ELEMS by construction

            int s  = idx % (KS * KS * KS);
            int ob = idx / (KS * KS * KS);
            int b  = ob % N_OUT;
            int o  = ob / N_OUT;

            float g0 = __ldg(grid_Rn + 0 * 125 + s);
            float g1 = __ldg(grid_Rn + 1 * 125 + s);
            float g2 = __ldg(grid_Rn + 2 * 125 + s);

            const float* R = out_H + b * 9;
            float c0 = __ldg(R + 0) * g0 + __ldg(R + 3) * g1 + __ldg(R + 6) * g2;
            float c1 = __ldg(R + 1) * g0 + __ldg(R + 4) * g1 + __ldg(R + 7) * g2;
            float c2 = __ldg(R + 2) * g0 + __ldg(R + 5) * g1 + __ldg(R + 8) * g2;

            float cz = (c0 + 1.0f) * 2.0f;
            float cy = (c1 + 1.0f) * 2.0f;
            float cx = (c2 + 1.0f) * 2.0f;
            float fz0 = floorf(cz), fy0 = floorf(cy), fx0 = floorf(cx);
            float fz = cz - fz0, fy = cy - fy0, fx = cx - fx0;
            int z0 = (int)fz0, y0 = (int)fy0, x0 = (int)fx0;

            const float* vol = weight_Rn + (size_t)o * 125;

            auto tap = [&](int iz, int iy, int ix) -> float {
                bool valid = (iz >= 0) & (iz < KS) & (iy >= 0) & (iy < KS) &
                             (ix >= 0) & (ix < KS);
                int zi = min(max(iz, 0), KS - 1);
                int yi = min(max(iy, 0), KS - 1);
                int xi = min(max(ix, 0), KS - 1);
                float v = __ldg(vol + zi * 25 + yi * 5 + xi);
                return valid ? v : 0.0f;
            };

            float r = tap(z0,     y0,     x0)     * (1.f - fz) * (1.f - fy) * (1.f - fx)
                    + tap(z0,     y0,     x0 + 1) * (1.f - fz) * (1.f - fy) * fx
                    + tap(z0,     y0 + 1, x0)     * (1.f - fz) * fy * (1.f - fx)
                    + tap(z0,     y0 + 1, x0 + 1) * (1.f - fz) * fy * fx
                    + tap(z0 + 1, y0,     x0)     * fz * (1.f - fy) * (1.f - fx)
                    + tap(z0 + 1, y0,     x0 + 1) * fz * (1.f - fy) * fx
                    + tap(z0 + 1, y0 + 1, x0)     * fz * fy * (1.f - fx)
                    + tap(z0 + 1, y0 + 1, x0 + 1) * fz * fy * fx;

            wout[idx] = r;
        }
        return;
    }

    // ================= wH role =================
    __shared__ float sw[C_IN * K_H];        // 3072 floats = 12 KB
    __shared__ int   snn[6 * N_OUT];        // 144 nn values for this block's 6 a

    int wb = bid - NB_WRN;
    int o  = wb >> 2;                       // 0..255
    int q  = wb & 3;                        // 0..3
    int aBase = q * 6;

    // 1) Issue weight stage loads into registers (768 float4, 2/thread exact).
    const float4* wsrc = (const float4*)(weight_H + (size_t)o * C_IN * K_H);
    float4 w0 = wsrc[tid];
    float4 w1 = wsrc[tid + NTHREADS];

    // 2) Compute this block's nn indices while those loads are in flight.
    //    pair t: a = aBase + t/24, b = t%24   (t < 144)
    if (tid < 6 * N_OUT) {
        int aLoc = tid / N_OUT;
        int b    = tid % N_OUT;
        const float* A = in_H  + (aBase + aLoc) * 9;  // in_H[a][j][k]
        const float* B = out_H + b * 9;               // out_H[b][j][i]
        float Av[9], Bv[9];
        #pragma unroll
        for (int e = 0; e < 9; e++) { Av[e] = __ldg(A + e); Bv[e] = __ldg(B + e); }
        // P[i][k] = sum_j B[j][i] * A[j][k]
        float P[9];
        #pragma unroll
        for (int i = 0; i < 3; i++)
            #pragma unroll
            for (int k = 0; k < 3; k++)
                P[i * 3 + k] = Bv[0 * 3 + i] * Av[0 * 3 + k]
                             + Bv[1 * 3 + i] * Av[1 * 3 + k]
                             + Bv[2 * 3 + i] * Av[2 * 3 + k];
        float best = -1e30f;
        int bi = 0;
        #pragma unroll 4
        for (int kh = 0; kh < K_H; kh++) {
            const float* G = grid_H + kh * 9;
            float s = 0.f;
            #pragma unroll
            for (int e = 0; e < 9; e++) s += P[e] * __ldg(G + e);
            if (s > best) { best = s; bi = kh; }   // strict >: first-max (JAX argmax)
        }
        snn[tid] = bi;
    }

    // 3) Commit staged weights to shared.
    float4* sw4 = (float4*)sw;
    sw4[tid] = w0;
    sw4[tid + NTHREADS] = w1;
    __syncthreads();

    // 4) Gather + coalesced float4 stores.
    //    v = ((a_local*128 + c)*6 + g); warp writes 512B contiguous.
    int g0i = tid % 6;
    int ac0 = tid / 6;                      // 0..63
    float4* dst4 = (float4*)out;

    for (int ac = ac0; ac < 6 * C_IN; ac += 64) {
        int c    = ac & (C_IN - 1);
        int aLoc = ac >> 7;
        const int*   nn = snn + aLoc * N_OUT + g0i * 4;
        const float* wr = sw + c * K_H;
        float4 r;
        r.x = wr[nn[0]];
        r.y = wr[nn[1]];
        r.z = wr[nn[2]];
        r.w = wr[nn[3]];
        size_t outIdx = ((size_t)(o * N_IN + aBase + aLoc) * C_IN + c) * (N_OUT / 4) + g0i;
        dst4[outIdx] = r;
    }
}

// ---------------------------------------------------------------------------
extern "C" void kernel_launch(void* const* d_in, const int* in_sizes, int n_in,
                              void* d_out, int out_size) {
    const float* in_H      = (const float*)d_in[0];   // [24,3,3]
    const float* out_H     = (const float*)d_in[1];   // [24,3,3]
    const float* grid_H    = (const float*)d_in[2];   // [24,3,3]
    const float* grid_Rn   = (const float*)d_in[3];   // [3,5,5,5]
    const float* weight_H  = (const float*)d_in[4];   // [256,128,24]
    const float* weight_Rn = (const float*)d_in[5];   // [256,1,5,5,5]
    float* out = (float*)d_out;

    fused_kernel<<<NB_WRN + NB_WH, NTHREADS>>>(in_H, out_H, grid_H, grid_Rn,
                                               weight_H, weight_Rn, out);
}